// round 11
// baseline (speedup 1.0000x reference)
#include <cuda_runtime.h>
#include <math.h>

#define N_USERS 50000
#define N_ENT   150000
#define NNODES  200000
#define D       64
#define NEDGE   3200000
#define BATCH   4096
#define NSLOTS  8192
#define CAP     128        // per-slot bucket capacity (Poisson(16): P(deg>128) ~ 1e-80)
#define OV_CAP  8192

// -------- scratch (device globals; no allocation allowed) --------
__device__ unsigned g_flag[(NNODES + 31) / 32];    // needed-dst bitset (25 KB)
__device__ int      g_slot[NNODES];                // node -> dense slot (valid iff flagged)
__device__ int      g_uniq[NSLOTS];                // slot -> node
__device__ int      g_nuniq;
__device__ int      g_cnt[NSLOTS];                 // per-slot taken-edge count
__device__ int      g_bin[NSLOTS * CAP];           // fixed-stride src buckets (4 MB)
__device__ int      g_nov;
__device__ int      g_ov_src[OV_CAP];
__device__ int      g_ov_slot[OV_CAP];
__device__ float    g_s1c[NNODES];                 // s1[n] + c1 (precomputed)
__device__ float    g_hd[NSLOTS * D];              // dense h_out (2 MB, L2-resident)
__device__ float    g_v1[D], g_v2[D];
__device__ float    g_c1, g_c2;

__device__ __forceinline__ const float2* feat2(int n, const float* ue, const float* ee) {
    return (n < N_USERS) ? (const float2*)ue + (size_t)n * 32
                         : (const float2*)ee + (size_t)(n - N_USERS) * 32;
}
__device__ __forceinline__ const float4* feat4(int n, const float* ue, const float* ee) {
    return (n < N_USERS) ? (const float4*)ue + (size_t)n * 16
                         : (const float4*)ee + (size_t)(n - N_USERS) * 16;
}

// -------- K0: zero scratch + compute v1,v2,c1,c2 --------
__global__ void k_init(const float* __restrict__ Wa, const float* __restrict__ ba,
                       const float* __restrict__ a) {
    int tid = blockIdx.x * blockDim.x + threadIdx.x;
    int stride = gridDim.x * blockDim.x;
    const int NW = (NNODES + 31) / 32;
    for (int i = tid; i < NW; i += stride) g_flag[i] = 0u;
    for (int i = tid; i < NSLOTS; i += stride) g_cnt[i] = 0;
    if (tid == 0) { g_nuniq = 0; g_nov = 0; }
    if (blockIdx.x == 0) {
        int k = threadIdx.x;
        if (k < D) {
            float v1 = 0.f, v2 = 0.f;
            for (int j = 0; j < D; j++) {
                float w = Wa[k * D + j];
                v1 += w * a[j];
                v2 += w * a[D + j];
            }
            g_v1[k] = v1; g_v2[k] = v2;
        }
        if (k == 0) {
            float c1 = 0.f, c2 = 0.f;
            for (int j = 0; j < D; j++) { c1 += ba[j] * a[j]; c2 += ba[j] * a[D + j]; }
            g_c1 = c1; g_c2 = c2;
        }
    }
}

// -------- K1: mark needed nodes, assign dense slots --------
__global__ void k_mark(const int* __restrict__ uid, const int* __restrict__ iid) {
    int i = blockIdx.x * blockDim.x + threadIdx.x;
    if (i >= 2 * BATCH) return;
    int node = (i < BATCH) ? uid[i] : N_USERS + iid[i - BATCH];
    unsigned bit = 1u << (node & 31);
    unsigned old = atomicOr(&g_flag[node >> 5], bit);
    if (!(old & bit)) {
        int slot = atomicAdd(&g_nuniq, 1);
        g_slot[node] = slot;
        g_uniq[slot] = node;
    }
}

// -------- K2: s1c[n] = dot(feat[n], v1) + c1  (float4 loads, 4 rows / warp / iter;
//              structure identical to the R4-passing k_s, single dot) --------
__global__ void __launch_bounds__(256) k_s(const float* __restrict__ ue, const float* __restrict__ ee) {
    int lane = threadIdx.x & 31;
    int half = lane >> 4;
    int l = lane & 15;
    int wg = (blockIdx.x * blockDim.x + threadIdx.x) >> 5;
    int nwarps = (gridDim.x * blockDim.x) >> 5;
    float4 v1 = ((const float4*)g_v1)[l];
    float c1 = g_c1;
    for (int n = wg * 4; n < NNODES; n += nwarps * 4) {   // NNODES % 4 == 0
        int ra = n + half;
        int rb = n + 2 + half;
        float4 fa = feat4(ra, ue, ee)[l];
        float4 fb = feat4(rb, ue, ee)[l];
        float a1 = fa.x * v1.x + fa.y * v1.y + fa.z * v1.z + fa.w * v1.w;
        float b1 = fb.x * v1.x + fb.y * v1.y + fb.z * v1.z + fb.w * v1.w;
        #pragma unroll
        for (int o = 8; o; o >>= 1) {   // reduce within each half-warp
            a1 += __shfl_xor_sync(0xFFFFFFFFu, a1, o);
            b1 += __shfl_xor_sync(0xFFFFFFFFu, b1, o);
        }
        if (l == 0) {
            g_s1c[ra] = a1 + c1;
            g_s1c[rb] = b1 + c1;
        }
    }
}

// -------- K3: edge stream — flag test + direct scatter (identical to R7/R9-passing) --------
__global__ void __launch_bounds__(256) k_edge1(const int* __restrict__ idx) {
    int gt = blockIdx.x * blockDim.x + threadIdx.x;
    int stride = gridDim.x * blockDim.x;
    for (int e = gt; e < NEDGE; e += stride) {
        int dst = idx[NEDGE + e];
        if ((g_flag[dst >> 5] >> (dst & 31)) & 1u) {
            int src = idx[e];
            int slot = g_slot[dst];
            int pos = atomicAdd(&g_cnt[slot], 1);
            if (pos < CAP) {
                g_bin[slot * CAP + pos] = src;
            } else {
                int op = atomicAdd(&g_nov, 1);
                if (op < OV_CAP) { g_ov_src[op] = src; g_ov_slot[op] = slot; }
            }
        }
    }
}

// -------- K4: warp-per-dst gather + fused epilogue (NO per-edge reductions) --------
__global__ void __launch_bounds__(256) k_gather(const float* __restrict__ ue, const float* __restrict__ ee,
                                                const float* __restrict__ W1, const float* __restrict__ b1,
                                                const float* __restrict__ W2, const float* __restrict__ b2) {
    __shared__ float sW1[D * D], sW2[D * D], sb1[D], sb2[D];
    __shared__ float sg[8][D];
    int tid = threadIdx.x, lane = tid & 31, wid = tid >> 5;
    for (int i = tid; i < D * D; i += 256) { sW1[i] = W1[i]; sW2[i] = W2[i]; }
    for (int i = tid; i < D; i += 256) { sb1[i] = b1[i]; sb2[i] = b2[i]; }
    __syncthreads();
    float2 v2 = ((const float2*)g_v2)[lane];
    float c2 = g_c2;
    int nu = g_nuniq;
    int nov = g_nov;
    if (nov > OV_CAP) nov = OV_CAP;
    int wg = (blockIdx.x * blockDim.x + tid) >> 5;
    int nwarps = (gridDim.x * blockDim.x) >> 5;
    for (int q = wg; q < nu; q += nwarps) {
        int n = g_uniq[q];
        float2 hs = feat2(n, ue, ee)[lane];
        float p = hs.x * v2.x + hs.y * v2.y;   // s2[dst] from its own row (once per slot)
        #pragma unroll
        for (int o = 16; o; o >>= 1) p += __shfl_xor_sync(0xFFFFFFFFu, p, o);
        float s2d = p + c2;
        int deg = g_cnt[q];
        if (deg > CAP) deg = CAP;
        const int* bs = g_bin + q * CAP;
        float ax = 0.f, ay = 0.f, den = 0.f;
        int e = 0;
        for (; e + 3 < deg; e += 4) {          // 4-way MLP, no reductions
            int s0 = bs[e], s1i = bs[e + 1], s2i = bs[e + 2], s3i = bs[e + 3];
            float a0 = g_s1c[s0], a1 = g_s1c[s1i], a2 = g_s1c[s2i], a3 = g_s1c[s3i];
            float2 f0 = feat2(s0,  ue, ee)[lane];
            float2 f1 = feat2(s1i, ue, ee)[lane];
            float2 f2 = feat2(s2i, ue, ee)[lane];
            float2 f3 = feat2(s3i, ue, ee)[lane];
            float e0 = a0 + s2d; e0 = (e0 > 0.f) ? e0 : 0.2f * e0;
            float e1 = a1 + s2d; e1 = (e1 > 0.f) ? e1 : 0.2f * e1;
            float e2 = a2 + s2d; e2 = (e2 > 0.f) ? e2 : 0.2f * e2;
            float e3 = a3 + s2d; e3 = (e3 > 0.f) ? e3 : 0.2f * e3;
            float x0 = __expf(e0), x1 = __expf(e1), x2 = __expf(e2), x3 = __expf(e3);
            den += (x0 + x1) + (x2 + x3);
            ax += x0 * f0.x + x1 * f1.x + x2 * f2.x + x3 * f3.x;
            ay += x0 * f0.y + x1 * f1.y + x2 * f2.y + x3 * f3.y;
        }
        for (; e < deg; e++) {
            int s0 = bs[e];
            float a0 = g_s1c[s0];
            float2 f0 = feat2(s0, ue, ee)[lane];
            float e0 = a0 + s2d; e0 = (e0 > 0.f) ? e0 : 0.2f * e0;
            float x0 = __expf(e0);
            den += x0; ax += x0 * f0.x; ay += x0 * f0.y;
        }
        // overflow edges (normally nov == 0): direct scan
        for (int i = 0; i < nov; i++) {
            if (g_ov_slot[i] == q) {
                int s0 = g_ov_src[i];
                float a0 = g_s1c[s0];
                float2 f0 = feat2(s0, ue, ee)[lane];
                float e0 = a0 + s2d; e0 = (e0 > 0.f) ? e0 : 0.2f * e0;
                float x0 = __expf(e0);
                den += x0; ax += x0 * f0.x; ay += x0 * f0.y;
            }
        }
        float inv = 1.f / (den + 1e-9f);
        float sden = den * inv;
        __syncwarp();
        sg[wid][2 * lane] = ax * inv;
        sg[wid][2 * lane + 1] = ay * inv;
        __syncwarp();
        float n0 = sden * sb1[2 * lane], n1 = sden * sb1[2 * lane + 1];
        #pragma unroll 16
        for (int k = 0; k < D; k++) {
            float gk = sg[wid][k];
            float2 wr = ((const float2*)(sW1 + k * D))[lane];
            n0 += gk * wr.x; n1 += gk * wr.y;
        }
        float sum0 = hs.x + n0, sum1 = hs.y + n1;
        float p0s = hs.x * n0, p1s = hs.y * n1;
        __syncwarp();
        sg[wid][2 * lane] = p0s;
        sg[wid][2 * lane + 1] = p1s;
        __syncwarp();
        float z0 = sum0 + sb2[2 * lane], z1 = sum1 + sb2[2 * lane + 1];
        #pragma unroll 16
        for (int k = 0; k < D; k++) {
            float pk = sg[wid][k];
            float2 wr = ((const float2*)(sW2 + k * D))[lane];
            z0 += pk * wr.x; z1 += pk * wr.y;
        }
        float h0 = (z0 > 0.f) ? z0 : 0.2f * z0;
        float h1 = (z1 > 0.f) ? z1 : 0.2f * z1;
        float ss = h0 * h0 + h1 * h1;
        #pragma unroll
        for (int o = 16; o; o >>= 1) ss += __shfl_xor_sync(0xFFFFFFFFu, ss, o);
        float invn = 1.f / fmaxf(sqrtf(ss), 1e-12f);
        float* orow = g_hd + (size_t)q * D;
        orow[2 * lane] = h0 * invn;
        orow[2 * lane + 1] = h1 * invn;
    }
}

// -------- K5: final pair dots (dense h_out via slot map) --------
__global__ void k_final(const int* __restrict__ uid, const int* __restrict__ iid,
                        const float* __restrict__ ue, const float* __restrict__ ee,
                        float* __restrict__ out) {
    int lane = threadIdx.x & 31;
    int wg = (blockIdx.x * blockDim.x + threadIdx.x) >> 5;
    int nwarps = (gridDim.x * blockDim.x) >> 5;
    for (int p = wg; p < BATCH; p += nwarps) {
        int un = uid[p];
        int in = N_USERS + iid[p];
        float2 fu = feat2(un, ue, ee)[lane];
        float2 fi = feat2(in, ue, ee)[lane];
        float acc = fu.x * fi.x + fu.y * fi.y;
        int su = g_slot[un], si = g_slot[in];
        float2 hu = ((const float2*)(g_hd + (size_t)su * D))[lane];
        float2 hi = ((const float2*)(g_hd + (size_t)si * D))[lane];
        acc += hu.x * hi.x + hu.y * hi.y;
        #pragma unroll
        for (int o = 16; o; o >>= 1) acc += __shfl_xor_sync(0xFFFFFFFFu, acc, o);
        if (lane == 0) out[p] = acc;
    }
}

extern "C" void kernel_launch(void* const* d_in, const int* in_sizes, int n_in,
                              void* d_out, int out_size) {
    const int* idx = (const int*)d_in[0];
    const int* uid = (const int*)d_in[1];
    const int* iid = (const int*)d_in[2];
    int base = (in_sizes[3] <= 2) ? 4 : 3;   // skip num_nodes scalar if present
    const float* ue = (const float*)d_in[base + 0];
    const float* ee = (const float*)d_in[base + 1];
    const float* Wa = (const float*)d_in[base + 2];
    const float* ba = (const float*)d_in[base + 3];
    const float* W1 = (const float*)d_in[base + 4];
    const float* b1 = (const float*)d_in[base + 5];
    const float* W2 = (const float*)d_in[base + 6];
    const float* b2 = (const float*)d_in[base + 7];
    const float* a  = (const float*)d_in[base + 8];
    float* out = (float*)d_out;
    (void)n_in; (void)out_size;

    k_init<<<64, 256>>>(Wa, ba, a);
    k_mark<<<32, 256>>>(uid, iid);
    k_s<<<2048, 256>>>(ue, ee);
    k_edge1<<<2048, 256>>>(idx);
    k_gather<<<1024, 256>>>(ue, ee, W1, b1, W2, b2);
    k_final<<<64, 256>>>(uid, iid, ue, ee, out);
}

// round 12
// speedup vs baseline: 1.0328x; 1.0328x over previous
#include <cuda_runtime.h>
#include <math.h>

#define N_USERS 50000
#define N_ENT   150000
#define NNODES  200000
#define D       64
#define NEDGE   3200000
#define BATCH   4096
#define NSLOTS  8192
#define CAP     128        // per-slot bucket capacity (Poisson(16): P(deg>128) ~ 1e-80)
#define OV_CAP  8192

// -------- scratch (device globals; no allocation allowed) --------
__device__ unsigned g_flag[(NNODES + 31) / 32];    // needed-dst bitset (25 KB)
__device__ int      g_slot[NNODES];                // node -> dense slot (valid iff flagged)
__device__ int      g_uniq[NSLOTS];                // slot -> node
__device__ int      g_nuniq;
__device__ int      g_cnt[NSLOTS];                 // per-slot taken-edge count
__device__ int      g_bin[NSLOTS * CAP];           // fixed-stride src buckets (4 MB)
__device__ int      g_nov;
__device__ int      g_ov_src[OV_CAP];
__device__ int      g_ov_slot[OV_CAP];
__device__ float    g_s1c[NNODES];                 // s1[n] + c1 (precomputed)
__device__ float    g_hd[NSLOTS * D];              // dense h_out (2 MB, L2-resident)
__device__ float    g_v1[D], g_v2[D];
__device__ float    g_c1, g_c2;

__device__ __forceinline__ const float2* feat2(int n, const float* ue, const float* ee) {
    return (n < N_USERS) ? (const float2*)ue + (size_t)n * 32
                         : (const float2*)ee + (size_t)(n - N_USERS) * 32;
}
__device__ __forceinline__ const float4* feat4(int n, const float* ue, const float* ee) {
    return (n < N_USERS) ? (const float4*)ue + (size_t)n * 16
                         : (const float4*)ee + (size_t)(n - N_USERS) * 16;
}

// -------- K0: zero scratch + compute v1,v2,c1,c2 --------
__global__ void k_init(const float* __restrict__ Wa, const float* __restrict__ ba,
                       const float* __restrict__ a) {
    int tid = blockIdx.x * blockDim.x + threadIdx.x;
    int stride = gridDim.x * blockDim.x;
    const int NW = (NNODES + 31) / 32;
    for (int i = tid; i < NW; i += stride) g_flag[i] = 0u;
    for (int i = tid; i < NSLOTS; i += stride) g_cnt[i] = 0;
    if (tid == 0) { g_nuniq = 0; g_nov = 0; }
    if (blockIdx.x == 0) {
        int k = threadIdx.x;
        if (k < D) {
            float v1 = 0.f, v2 = 0.f;
            for (int j = 0; j < D; j++) {
                float w = Wa[k * D + j];
                v1 += w * a[j];
                v2 += w * a[D + j];
            }
            g_v1[k] = v1; g_v2[k] = v2;
        }
        if (k == 0) {
            float c1 = 0.f, c2 = 0.f;
            for (int j = 0; j < D; j++) { c1 += ba[j] * a[j]; c2 += ba[j] * a[D + j]; }
            g_c1 = c1; g_c2 = c2;
        }
    }
}

// -------- K1: mark needed nodes, assign dense slots --------
__global__ void k_mark(const int* __restrict__ uid, const int* __restrict__ iid) {
    int i = blockIdx.x * blockDim.x + threadIdx.x;
    if (i >= 2 * BATCH) return;
    int node = (i < BATCH) ? uid[i] : N_USERS + iid[i - BATCH];
    unsigned bit = 1u << (node & 31);
    unsigned old = atomicOr(&g_flag[node >> 5], bit);
    if (!(old & bit)) {
        int slot = atomicAdd(&g_nuniq, 1);
        g_slot[node] = slot;
        g_uniq[slot] = node;
    }
}

// -------- K2: s1c[n] = dot(feat[n], v1) + c1 (identical to R11-passing) --------
__global__ void __launch_bounds__(256) k_s(const float* __restrict__ ue, const float* __restrict__ ee) {
    int lane = threadIdx.x & 31;
    int half = lane >> 4;
    int l = lane & 15;
    int wg = (blockIdx.x * blockDim.x + threadIdx.x) >> 5;
    int nwarps = (gridDim.x * blockDim.x) >> 5;
    float4 v1 = ((const float4*)g_v1)[l];
    float c1 = g_c1;
    for (int n = wg * 4; n < NNODES; n += nwarps * 4) {   // NNODES % 4 == 0
        int ra = n + half;
        int rb = n + 2 + half;
        float4 fa = feat4(ra, ue, ee)[l];
        float4 fb = feat4(rb, ue, ee)[l];
        float a1 = fa.x * v1.x + fa.y * v1.y + fa.z * v1.z + fa.w * v1.w;
        float b1 = fb.x * v1.x + fb.y * v1.y + fb.z * v1.z + fb.w * v1.w;
        #pragma unroll
        for (int o = 8; o; o >>= 1) {   // reduce within each half-warp
            a1 += __shfl_xor_sync(0xFFFFFFFFu, a1, o);
            b1 += __shfl_xor_sync(0xFFFFFFFFu, b1, o);
        }
        if (l == 0) {
            g_s1c[ra] = a1 + c1;
            g_s1c[rb] = b1 + c1;
        }
    }
}

// -------- K3: edge stream — int4 loads for MLP, conditional src load, no barriers --------
__global__ void __launch_bounds__(256) k_edge1(const int* __restrict__ idx) {
    const int NI4 = NEDGE / 4;                      // 800000 (NEDGE % 4 == 0)
    int gt = blockIdx.x * blockDim.x + threadIdx.x;
    int stride = gridDim.x * blockDim.x;
    const int4* s4p = (const int4*)idx;
    const int4* d4p = (const int4*)(idx + NEDGE);
    for (int i = gt; i < NI4; i += stride) {
        int4 d4 = d4p[i];
        // 4 independent flag gathers (all depend only on the one 16B load)
        unsigned t0 = (g_flag[d4.x >> 5] >> (d4.x & 31)) & 1u;
        unsigned t1 = (g_flag[d4.y >> 5] >> (d4.y & 31)) & 1u;
        unsigned t2 = (g_flag[d4.z >> 5] >> (d4.z & 31)) & 1u;
        unsigned t3 = (g_flag[d4.w >> 5] >> (d4.w & 31)) & 1u;
        if (t0 | t1 | t2 | t3) {
            int4 s4 = s4p[i];                       // load srcs only when needed (~15%)
            int dd[4] = { d4.x, d4.y, d4.z, d4.w };
            int ss[4] = { s4.x, s4.y, s4.z, s4.w };
            unsigned tt[4] = { t0, t1, t2, t3 };
            #pragma unroll
            for (int j = 0; j < 4; j++) {
                if (tt[j]) {
                    int slot = g_slot[dd[j]];
                    int pos = atomicAdd(&g_cnt[slot], 1);
                    if (pos < CAP) {
                        g_bin[slot * CAP + pos] = ss[j];
                    } else {
                        int op = atomicAdd(&g_nov, 1);
                        if (op < OV_CAP) { g_ov_src[op] = ss[j]; g_ov_slot[op] = slot; }
                    }
                }
            }
        }
    }
}

// -------- K4: warp-per-dst gather + fused epilogue (identical to R11-passing) --------
__global__ void __launch_bounds__(256) k_gather(const float* __restrict__ ue, const float* __restrict__ ee,
                                                const float* __restrict__ W1, const float* __restrict__ b1,
                                                const float* __restrict__ W2, const float* __restrict__ b2) {
    __shared__ float sW1[D * D], sW2[D * D], sb1[D], sb2[D];
    __shared__ float sg[8][D];
    int tid = threadIdx.x, lane = tid & 31, wid = tid >> 5;
    for (int i = tid; i < D * D; i += 256) { sW1[i] = W1[i]; sW2[i] = W2[i]; }
    for (int i = tid; i < D; i += 256) { sb1[i] = b1[i]; sb2[i] = b2[i]; }
    __syncthreads();
    float2 v2 = ((const float2*)g_v2)[lane];
    float c2 = g_c2;
    int nu = g_nuniq;
    int nov = g_nov;
    if (nov > OV_CAP) nov = OV_CAP;
    int wg = (blockIdx.x * blockDim.x + tid) >> 5;
    int nwarps = (gridDim.x * blockDim.x) >> 5;
    for (int q = wg; q < nu; q += nwarps) {
        int n = g_uniq[q];
        float2 hs = feat2(n, ue, ee)[lane];
        float p = hs.x * v2.x + hs.y * v2.y;   // s2[dst] from its own row (once per slot)
        #pragma unroll
        for (int o = 16; o; o >>= 1) p += __shfl_xor_sync(0xFFFFFFFFu, p, o);
        float s2d = p + c2;
        int deg = g_cnt[q];
        if (deg > CAP) deg = CAP;
        const int* bs = g_bin + q * CAP;
        float ax = 0.f, ay = 0.f, den = 0.f;
        int e = 0;
        for (; e + 3 < deg; e += 4) {          // 4-way MLP, no reductions
            int s0 = bs[e], s1i = bs[e + 1], s2i = bs[e + 2], s3i = bs[e + 3];
            float a0 = g_s1c[s0], a1 = g_s1c[s1i], a2 = g_s1c[s2i], a3 = g_s1c[s3i];
            float2 f0 = feat2(s0,  ue, ee)[lane];
            float2 f1 = feat2(s1i, ue, ee)[lane];
            float2 f2 = feat2(s2i, ue, ee)[lane];
            float2 f3 = feat2(s3i, ue, ee)[lane];
            float e0 = a0 + s2d; e0 = (e0 > 0.f) ? e0 : 0.2f * e0;
            float e1 = a1 + s2d; e1 = (e1 > 0.f) ? e1 : 0.2f * e1;
            float e2 = a2 + s2d; e2 = (e2 > 0.f) ? e2 : 0.2f * e2;
            float e3 = a3 + s2d; e3 = (e3 > 0.f) ? e3 : 0.2f * e3;
            float x0 = __expf(e0), x1 = __expf(e1), x2 = __expf(e2), x3 = __expf(e3);
            den += (x0 + x1) + (x2 + x3);
            ax += x0 * f0.x + x1 * f1.x + x2 * f2.x + x3 * f3.x;
            ay += x0 * f0.y + x1 * f1.y + x2 * f2.y + x3 * f3.y;
        }
        for (; e < deg; e++) {
            int s0 = bs[e];
            float a0 = g_s1c[s0];
            float2 f0 = feat2(s0, ue, ee)[lane];
            float e0 = a0 + s2d; e0 = (e0 > 0.f) ? e0 : 0.2f * e0;
            float x0 = __expf(e0);
            den += x0; ax += x0 * f0.x; ay += x0 * f0.y;
        }
        // overflow edges (normally nov == 0): direct scan
        for (int i = 0; i < nov; i++) {
            if (g_ov_slot[i] == q) {
                int s0 = g_ov_src[i];
                float a0 = g_s1c[s0];
                float2 f0 = feat2(s0, ue, ee)[lane];
                float e0 = a0 + s2d; e0 = (e0 > 0.f) ? e0 : 0.2f * e0;
                float x0 = __expf(e0);
                den += x0; ax += x0 * f0.x; ay += x0 * f0.y;
            }
        }
        float inv = 1.f / (den + 1e-9f);
        float sden = den * inv;
        __syncwarp();
        sg[wid][2 * lane] = ax * inv;
        sg[wid][2 * lane + 1] = ay * inv;
        __syncwarp();
        float n0 = sden * sb1[2 * lane], n1 = sden * sb1[2 * lane + 1];
        #pragma unroll 16
        for (int k = 0; k < D; k++) {
            float gk = sg[wid][k];
            float2 wr = ((const float2*)(sW1 + k * D))[lane];
            n0 += gk * wr.x; n1 += gk * wr.y;
        }
        float sum0 = hs.x + n0, sum1 = hs.y + n1;
        float p0s = hs.x * n0, p1s = hs.y * n1;
        __syncwarp();
        sg[wid][2 * lane] = p0s;
        sg[wid][2 * lane + 1] = p1s;
        __syncwarp();
        float z0 = sum0 + sb2[2 * lane], z1 = sum1 + sb2[2 * lane + 1];
        #pragma unroll 16
        for (int k = 0; k < D; k++) {
            float pk = sg[wid][k];
            float2 wr = ((const float2*)(sW2 + k * D))[lane];
            z0 += pk * wr.x; z1 += pk * wr.y;
        }
        float h0 = (z0 > 0.f) ? z0 : 0.2f * z0;
        float h1 = (z1 > 0.f) ? z1 : 0.2f * z1;
        float ss = h0 * h0 + h1 * h1;
        #pragma unroll
        for (int o = 16; o; o >>= 1) ss += __shfl_xor_sync(0xFFFFFFFFu, ss, o);
        float invn = 1.f / fmaxf(sqrtf(ss), 1e-12f);
        float* orow = g_hd + (size_t)q * D;
        orow[2 * lane] = h0 * invn;
        orow[2 * lane + 1] = h1 * invn;
    }
}

// -------- K5: final pair dots (identical to R11-passing) --------
__global__ void k_final(const int* __restrict__ uid, const int* __restrict__ iid,
                        const float* __restrict__ ue, const float* __restrict__ ee,
                        float* __restrict__ out) {
    int lane = threadIdx.x & 31;
    int wg = (blockIdx.x * blockDim.x + threadIdx.x) >> 5;
    int nwarps = (gridDim.x * blockDim.x) >> 5;
    for (int p = wg; p < BATCH; p += nwarps) {
        int un = uid[p];
        int in = N_USERS + iid[p];
        float2 fu = feat2(un, ue, ee)[lane];
        float2 fi = feat2(in, ue, ee)[lane];
        float acc = fu.x * fi.x + fu.y * fi.y;
        int su = g_slot[un], si = g_slot[in];
        float2 hu = ((const float2*)(g_hd + (size_t)su * D))[lane];
        float2 hi = ((const float2*)(g_hd + (size_t)si * D))[lane];
        acc += hu.x * hi.x + hu.y * hi.y;
        #pragma unroll
        for (int o = 16; o; o >>= 1) acc += __shfl_xor_sync(0xFFFFFFFFu, acc, o);
        if (lane == 0) out[p] = acc;
    }
}

extern "C" void kernel_launch(void* const* d_in, const int* in_sizes, int n_in,
                              void* d_out, int out_size) {
    const int* idx = (const int*)d_in[0];
    const int* uid = (const int*)d_in[1];
    const int* iid = (const int*)d_in[2];
    int base = (in_sizes[3] <= 2) ? 4 : 3;   // skip num_nodes scalar if present
    const float* ue = (const float*)d_in[base + 0];
    const float* ee = (const float*)d_in[base + 1];
    const float* Wa = (const float*)d_in[base + 2];
    const float* ba = (const float*)d_in[base + 3];
    const float* W1 = (const float*)d_in[base + 4];
    const float* b1 = (const float*)d_in[base + 5];
    const float* W2 = (const float*)d_in[base + 6];
    const float* b2 = (const float*)d_in[base + 7];
    const float* a  = (const float*)d_in[base + 8];
    float* out = (float*)d_out;
    (void)n_in; (void)out_size;

    k_init<<<64, 256>>>(Wa, ba, a);
    k_mark<<<32, 256>>>(uid, iid);
    k_s<<<2048, 256>>>(ue, ee);
    k_edge1<<<2048, 256>>>(idx);
    k_gather<<<1024, 256>>>(ue, ee, W1, b1, W2, b2);
    k_final<<<64, 256>>>(uid, iid, ue, ee, out);
}

// round 13
// speedup vs baseline: 1.1302x; 1.0944x over previous
#include <cuda_runtime.h>
#include <math.h>

#define N_USERS 50000
#define N_ENT   150000
#define NNODES  200000
#define D       64
#define NEDGE   3200000
#define BATCH   4096
#define NSLOTS  8192
#define CAP     128        // per-slot bucket capacity (Poisson(16): P(deg>128) ~ 1e-80)
#define OV_CAP  8192
#define EDGE_BLOCKS 800    // edge-stream blocks inside fused k_stream
#define KS_BLOCKS   2048   // s1c blocks inside fused k_stream

// -------- scratch (device globals; zero-init at load; each replay restores zeros) ----
__device__ unsigned g_flag[(NNODES + 31) / 32];    // needed-dst bitset (25 KB)
__device__ int      g_slot[NNODES];                // node -> dense slot (valid iff flagged)
__device__ int      g_uniq[NSLOTS];                // slot -> node
__device__ int      g_nuniq;
__device__ int      g_cnt[NSLOTS];                 // per-slot taken-edge count
__device__ int      g_bin[NSLOTS * CAP];           // fixed-stride src buckets (4 MB)
__device__ int      g_nov;
__device__ int      g_ov_src[OV_CAP];
__device__ int      g_ov_slot[OV_CAP];
__device__ float    g_s1c[NNODES];                 // s1[n] + c1 (precomputed)
__device__ float    g_hd[NSLOTS * D];              // dense h_out (2 MB, L2-resident)
__device__ float    g_v1[D], g_v2[D];
__device__ float    g_c1, g_c2;

__device__ __forceinline__ const float2* feat2(int n, const float* ue, const float* ee) {
    return (n < N_USERS) ? (const float2*)ue + (size_t)n * 32
                         : (const float2*)ee + (size_t)(n - N_USERS) * 32;
}
__device__ __forceinline__ const float4* feat4(int n, const float* ue, const float* ee) {
    return (n < N_USERS) ? (const float4*)ue + (size_t)n * 16
                         : (const float4*)ee + (size_t)(n - N_USERS) * 16;
}

// -------- K0: mark needed nodes + (block 32) compute v1,v2,c1,c2 --------
__global__ void k_mark(const int* __restrict__ uid, const int* __restrict__ iid,
                       const float* __restrict__ Wa, const float* __restrict__ ba,
                       const float* __restrict__ a) {
    if (blockIdx.x == 32) {
        int k = threadIdx.x;
        if (k < D) {
            float v1 = 0.f, v2 = 0.f;
            for (int j = 0; j < D; j++) {
                float w = Wa[k * D + j];
                v1 += w * a[j];
                v2 += w * a[D + j];
            }
            g_v1[k] = v1; g_v2[k] = v2;
        }
        if (k == 0) {
            float c1 = 0.f, c2 = 0.f;
            for (int j = 0; j < D; j++) { c1 += ba[j] * a[j]; c2 += ba[j] * a[D + j]; }
            g_c1 = c1; g_c2 = c2;
        }
        return;
    }
    int i = blockIdx.x * blockDim.x + threadIdx.x;
    if (i >= 2 * BATCH) return;
    int node = (i < BATCH) ? uid[i] : N_USERS + iid[i - BATCH];
    unsigned bit = 1u << (node & 31);
    unsigned old = atomicOr(&g_flag[node >> 5], bit);
    if (!(old & bit)) {
        int slot = atomicAdd(&g_nuniq, 1);
        g_slot[node] = slot;
        g_uniq[slot] = node;
    }
}

// -------- K1 (fused): blocks [0,EDGE_BLOCKS) stream edges; rest compute s1c --------
__global__ void __launch_bounds__(256) k_stream(const int* __restrict__ idx,
                                                const float* __restrict__ ue,
                                                const float* __restrict__ ee) {
    if (blockIdx.x < EDGE_BLOCKS) {
        // ---- edge part: 4 upfront int4 dst loads per thread, conditional src ----
        const int NI4 = NEDGE / 4;                       // 800000
        const int TOT = EDGE_BLOCKS * 256;               // 204800 threads
        int gt = blockIdx.x * 256 + threadIdx.x;
        const int4* s4p = (const int4*)idx;
        const int4* d4p = (const int4*)(idx + NEDGE);
        int4 d[4]; bool v[4];
        #pragma unroll
        for (int k = 0; k < 4; k++) {
            int i = gt + k * TOT;
            v[k] = (i < NI4);
            if (v[k]) d[k] = d4p[i];                     // 4 independent 16B loads
        }
        #pragma unroll
        for (int k = 0; k < 4; k++) {
            if (!v[k]) continue;
            int4 d4 = d[k];
            unsigned t0 = (g_flag[d4.x >> 5] >> (d4.x & 31)) & 1u;
            unsigned t1 = (g_flag[d4.y >> 5] >> (d4.y & 31)) & 1u;
            unsigned t2 = (g_flag[d4.z >> 5] >> (d4.z & 31)) & 1u;
            unsigned t3 = (g_flag[d4.w >> 5] >> (d4.w & 31)) & 1u;
            if (t0 | t1 | t2 | t3) {
                int4 s4 = s4p[gt + k * TOT];             // src only when needed (~15%)
                int dd[4] = { d4.x, d4.y, d4.z, d4.w };
                int ss[4] = { s4.x, s4.y, s4.z, s4.w };
                unsigned tt[4] = { t0, t1, t2, t3 };
                #pragma unroll
                for (int j = 0; j < 4; j++) {
                    if (tt[j]) {
                        int slot = g_slot[dd[j]];
                        int pos = atomicAdd(&g_cnt[slot], 1);
                        if (pos < CAP) {
                            g_bin[slot * CAP + pos] = ss[j];
                        } else {
                            int op = atomicAdd(&g_nov, 1);
                            if (op < OV_CAP) { g_ov_src[op] = ss[j]; g_ov_slot[op] = slot; }
                        }
                    }
                }
            }
        }
    } else {
        // ---- s1c part: identical structure to the R11/R12-passing k_s ----
        int lane = threadIdx.x & 31;
        int half = lane >> 4;
        int l = lane & 15;
        int vb = blockIdx.x - EDGE_BLOCKS;
        int wg = (vb * 256 + threadIdx.x) >> 5;
        int nwarps = KS_BLOCKS * 8;
        float4 v1 = ((const float4*)g_v1)[l];
        float c1 = g_c1;
        for (int n = wg * 4; n < NNODES; n += nwarps * 4) {   // NNODES % 4 == 0
            int ra = n + half;
            int rb = n + 2 + half;
            float4 fa = feat4(ra, ue, ee)[l];
            float4 fb = feat4(rb, ue, ee)[l];
            float a1 = fa.x * v1.x + fa.y * v1.y + fa.z * v1.z + fa.w * v1.w;
            float b1 = fb.x * v1.x + fb.y * v1.y + fb.z * v1.z + fb.w * v1.w;
            #pragma unroll
            for (int o = 8; o; o >>= 1) {   // reduce within each half-warp
                a1 += __shfl_xor_sync(0xFFFFFFFFu, a1, o);
                b1 += __shfl_xor_sync(0xFFFFFFFFu, b1, o);
            }
            if (l == 0) {
                g_s1c[ra] = a1 + c1;
                g_s1c[rb] = b1 + c1;
            }
        }
    }
}

// -------- K2: warp-per-dst gather + fused epilogue + per-slot state cleanup --------
__global__ void __launch_bounds__(256) k_gather(const float* __restrict__ ue, const float* __restrict__ ee,
                                                const float* __restrict__ W1, const float* __restrict__ b1,
                                                const float* __restrict__ W2, const float* __restrict__ b2) {
    __shared__ float sW1[D * D], sW2[D * D], sb1[D], sb2[D];
    __shared__ float sg[8][D];
    int tid = threadIdx.x, lane = tid & 31, wid = tid >> 5;
    for (int i = tid; i < D * D; i += 256) { sW1[i] = W1[i]; sW2[i] = W2[i]; }
    for (int i = tid; i < D; i += 256) { sb1[i] = b1[i]; sb2[i] = b2[i]; }
    __syncthreads();
    float2 v2 = ((const float2*)g_v2)[lane];
    float c2 = g_c2;
    int nu = g_nuniq;
    int nov = g_nov;
    if (nov > OV_CAP) nov = OV_CAP;
    int wg = (blockIdx.x * blockDim.x + tid) >> 5;
    int nwarps = (gridDim.x * blockDim.x) >> 5;
    for (int q = wg; q < nu; q += nwarps) {
        int n = g_uniq[q];
        float2 hs = feat2(n, ue, ee)[lane];
        float p = hs.x * v2.x + hs.y * v2.y;   // s2[dst] from its own row (once per slot)
        #pragma unroll
        for (int o = 16; o; o >>= 1) p += __shfl_xor_sync(0xFFFFFFFFu, p, o);
        float s2d = p + c2;
        int deg = g_cnt[q];
        if (deg > CAP) deg = CAP;
        const int* bs = g_bin + q * CAP;
        float ax = 0.f, ay = 0.f, den = 0.f;
        int e = 0;
        for (; e + 3 < deg; e += 4) {          // 4-way MLP, no reductions
            int s0 = bs[e], s1i = bs[e + 1], s2i = bs[e + 2], s3i = bs[e + 3];
            float a0 = g_s1c[s0], a1 = g_s1c[s1i], a2 = g_s1c[s2i], a3 = g_s1c[s3i];
            float2 f0 = feat2(s0,  ue, ee)[lane];
            float2 f1 = feat2(s1i, ue, ee)[lane];
            float2 f2 = feat2(s2i, ue, ee)[lane];
            float2 f3 = feat2(s3i, ue, ee)[lane];
            float e0 = a0 + s2d; e0 = (e0 > 0.f) ? e0 : 0.2f * e0;
            float e1 = a1 + s2d; e1 = (e1 > 0.f) ? e1 : 0.2f * e1;
            float e2 = a2 + s2d; e2 = (e2 > 0.f) ? e2 : 0.2f * e2;
            float e3 = a3 + s2d; e3 = (e3 > 0.f) ? e3 : 0.2f * e3;
            float x0 = __expf(e0), x1 = __expf(e1), x2 = __expf(e2), x3 = __expf(e3);
            den += (x0 + x1) + (x2 + x3);
            ax += x0 * f0.x + x1 * f1.x + x2 * f2.x + x3 * f3.x;
            ay += x0 * f0.y + x1 * f1.y + x2 * f2.y + x3 * f3.y;
        }
        for (; e < deg; e++) {
            int s0 = bs[e];
            float a0 = g_s1c[s0];
            float2 f0 = feat2(s0, ue, ee)[lane];
            float e0 = a0 + s2d; e0 = (e0 > 0.f) ? e0 : 0.2f * e0;
            float x0 = __expf(e0);
            den += x0; ax += x0 * f0.x; ay += x0 * f0.y;
        }
        // overflow edges (normally nov == 0): direct scan
        for (int i = 0; i < nov; i++) {
            if (g_ov_slot[i] == q) {
                int s0 = g_ov_src[i];
                float a0 = g_s1c[s0];
                float2 f0 = feat2(s0, ue, ee)[lane];
                float e0 = a0 + s2d; e0 = (e0 > 0.f) ? e0 : 0.2f * e0;
                float x0 = __expf(e0);
                den += x0; ax += x0 * f0.x; ay += x0 * f0.y;
            }
        }
        // restore clean state for next replay (graph-deterministic)
        if (lane == 0) { g_cnt[q] = 0; g_flag[n >> 5] = 0u; }
        float inv = 1.f / (den + 1e-9f);
        float sden = den * inv;
        __syncwarp();
        sg[wid][2 * lane] = ax * inv;
        sg[wid][2 * lane + 1] = ay * inv;
        __syncwarp();
        float n0 = sden * sb1[2 * lane], n1 = sden * sb1[2 * lane + 1];
        #pragma unroll 16
        for (int k = 0; k < D; k++) {
            float gk = sg[wid][k];
            float2 wr = ((const float2*)(sW1 + k * D))[lane];
            n0 += gk * wr.x; n1 += gk * wr.y;
        }
        float sum0 = hs.x + n0, sum1 = hs.y + n1;
        float p0s = hs.x * n0, p1s = hs.y * n1;
        __syncwarp();
        sg[wid][2 * lane] = p0s;
        sg[wid][2 * lane + 1] = p1s;
        __syncwarp();
        float z0 = sum0 + sb2[2 * lane], z1 = sum1 + sb2[2 * lane + 1];
        #pragma unroll 16
        for (int k = 0; k < D; k++) {
            float pk = sg[wid][k];
            float2 wr = ((const float2*)(sW2 + k * D))[lane];
            z0 += pk * wr.x; z1 += pk * wr.y;
        }
        float h0 = (z0 > 0.f) ? z0 : 0.2f * z0;
        float h1 = (z1 > 0.f) ? z1 : 0.2f * z1;
        float ss = h0 * h0 + h1 * h1;
        #pragma unroll
        for (int o = 16; o; o >>= 1) ss += __shfl_xor_sync(0xFFFFFFFFu, ss, o);
        float invn = 1.f / fmaxf(sqrtf(ss), 1e-12f);
        float* orow = g_hd + (size_t)q * D;
        orow[2 * lane] = h0 * invn;
        orow[2 * lane + 1] = h1 * invn;
    }
}

// -------- K3: final pair dots + counter cleanup --------
__global__ void k_final(const int* __restrict__ uid, const int* __restrict__ iid,
                        const float* __restrict__ ue, const float* __restrict__ ee,
                        float* __restrict__ out) {
    if (blockIdx.x == 0 && threadIdx.x == 0) { g_nuniq = 0; g_nov = 0; }
    int lane = threadIdx.x & 31;
    int wg = (blockIdx.x * blockDim.x + threadIdx.x) >> 5;
    int nwarps = (gridDim.x * blockDim.x) >> 5;
    for (int p = wg; p < BATCH; p += nwarps) {
        int un = uid[p];
        int in = N_USERS + iid[p];
        float2 fu = feat2(un, ue, ee)[lane];
        float2 fi = feat2(in, ue, ee)[lane];
        float acc = fu.x * fi.x + fu.y * fi.y;
        int su = g_slot[un], si = g_slot[in];
        float2 hu = ((const float2*)(g_hd + (size_t)su * D))[lane];
        float2 hi = ((const float2*)(g_hd + (size_t)si * D))[lane];
        acc += hu.x * hi.x + hu.y * hi.y;
        #pragma unroll
        for (int o = 16; o; o >>= 1) acc += __shfl_xor_sync(0xFFFFFFFFu, acc, o);
        if (lane == 0) out[p] = acc;
    }
}

extern "C" void kernel_launch(void* const* d_in, const int* in_sizes, int n_in,
                              void* d_out, int out_size) {
    const int* idx = (const int*)d_in[0];
    const int* uid = (const int*)d_in[1];
    const int* iid = (const int*)d_in[2];
    int base = (in_sizes[3] <= 2) ? 4 : 3;   // skip num_nodes scalar if present
    const float* ue = (const float*)d_in[base + 0];
    const float* ee = (const float*)d_in[base + 1];
    const float* Wa = (const float*)d_in[base + 2];
    const float* ba = (const float*)d_in[base + 3];
    const float* W1 = (const float*)d_in[base + 4];
    const float* b1 = (const float*)d_in[base + 5];
    const float* W2 = (const float*)d_in[base + 6];
    const float* b2 = (const float*)d_in[base + 7];
    const float* a  = (const float*)d_in[base + 8];
    float* out = (float*)d_out;
    (void)n_in; (void)out_size;

    k_mark<<<33, 256>>>(uid, iid, Wa, ba, a);
    k_stream<<<EDGE_BLOCKS + KS_BLOCKS, 256>>>(idx, ue, ee);
    k_gather<<<1024, 256>>>(ue, ee, W1, b1, W2, b2);
    k_final<<<64, 256>>>(uid, iid, ue, ee, out);
}

// round 14
// speedup vs baseline: 1.2308x; 1.0889x over previous
#include <cuda_runtime.h>
#include <math.h>

#define N_USERS 50000
#define N_ENT   150000
#define NNODES  200000
#define D       64
#define NEDGE   3200000
#define BATCH   4096
#define NSLOTS  8192
#define CAP     128        // per-slot bucket capacity (Poisson(16): P(deg>128) ~ 1e-80)
#define OV_CAP  8192
#define EDGE_BLOCKS 800    // edge-stream blocks inside fused k_stream
#define KS_BLOCKS   2048   // s1c blocks inside fused k_stream

// -------- scratch (device globals; zero-init at load; each replay restores zeros) ----
__device__ unsigned g_flag[(NNODES + 31) / 32];    // needed-dst bitset (25 KB)
__device__ int      g_slot[NNODES];                // node -> dense slot (valid iff flagged)
__device__ int      g_uniq[NSLOTS];                // slot -> node
__device__ int      g_nuniq;
__device__ int      g_cnt[NSLOTS];                 // per-slot taken-edge count
__device__ int      g_bin[NSLOTS * CAP];           // fixed-stride src buckets (4 MB)
__device__ int      g_nov;
__device__ int      g_ov_src[OV_CAP];
__device__ int      g_ov_slot[OV_CAP];
__device__ float    g_s1c[NNODES];                 // s1[n] + c1 (precomputed)
__device__ float    g_hd[NSLOTS * D];              // dense h_out (2 MB, L2-resident)
__device__ float    g_v1[D], g_v2[D];
__device__ float    g_c1, g_c2;

__device__ __forceinline__ const float2* feat2(int n, const float* ue, const float* ee) {
    return (n < N_USERS) ? (const float2*)ue + (size_t)n * 32
                         : (const float2*)ee + (size_t)(n - N_USERS) * 32;
}
__device__ __forceinline__ const float4* feat4(int n, const float* ue, const float* ee) {
    return (n < N_USERS) ? (const float4*)ue + (size_t)n * 16
                         : (const float4*)ee + (size_t)(n - N_USERS) * 16;
}

// -------- K0: mark needed nodes + (block 32) compute v1,v2,c1,c2 --------
__global__ void k_mark(const int* __restrict__ uid, const int* __restrict__ iid,
                       const float* __restrict__ Wa, const float* __restrict__ ba,
                       const float* __restrict__ a) {
    if (blockIdx.x == 32) {
        int k = threadIdx.x;
        if (k < D) {
            float v1 = 0.f, v2 = 0.f;
            for (int j = 0; j < D; j++) {
                float w = Wa[k * D + j];
                v1 += w * a[j];
                v2 += w * a[D + j];
            }
            g_v1[k] = v1; g_v2[k] = v2;
        }
        if (k == 0) {
            float c1 = 0.f, c2 = 0.f;
            for (int j = 0; j < D; j++) { c1 += ba[j] * a[j]; c2 += ba[j] * a[D + j]; }
            g_c1 = c1; g_c2 = c2;
        }
        return;
    }
    int i = blockIdx.x * blockDim.x + threadIdx.x;
    if (i >= 2 * BATCH) return;
    int node = (i < BATCH) ? uid[i] : N_USERS + iid[i - BATCH];
    unsigned bit = 1u << (node & 31);
    unsigned old = atomicOr(&g_flag[node >> 5], bit);
    if (!(old & bit)) {
        int slot = atomicAdd(&g_nuniq, 1);
        g_slot[node] = slot;
        g_uniq[slot] = node;
    }
}

// -------- K1 (fused): blocks [0,EDGE_BLOCKS) stream edges; rest compute s1c --------
__global__ void __launch_bounds__(256) k_stream(const int* __restrict__ idx,
                                                const float* __restrict__ ue,
                                                const float* __restrict__ ee) {
    if (blockIdx.x < EDGE_BLOCKS) {
        // ---- edge part: 4 upfront int4 dst loads per thread, conditional src ----
        const int NI4 = NEDGE / 4;                       // 800000
        const int TOT = EDGE_BLOCKS * 256;               // 204800 threads
        int gt = blockIdx.x * 256 + threadIdx.x;
        const int4* s4p = (const int4*)idx;
        const int4* d4p = (const int4*)(idx + NEDGE);
        int4 d[4]; bool v[4];
        #pragma unroll
        for (int k = 0; k < 4; k++) {
            int i = gt + k * TOT;
            v[k] = (i < NI4);
            if (v[k]) d[k] = d4p[i];                     // 4 independent 16B loads
        }
        #pragma unroll
        for (int k = 0; k < 4; k++) {
            if (!v[k]) continue;
            int4 d4 = d[k];
            unsigned t0 = (g_flag[d4.x >> 5] >> (d4.x & 31)) & 1u;
            unsigned t1 = (g_flag[d4.y >> 5] >> (d4.y & 31)) & 1u;
            unsigned t2 = (g_flag[d4.z >> 5] >> (d4.z & 31)) & 1u;
            unsigned t3 = (g_flag[d4.w >> 5] >> (d4.w & 31)) & 1u;
            if (t0 | t1 | t2 | t3) {
                int4 s4 = s4p[gt + k * TOT];             // src only when needed (~15%)
                int dd[4] = { d4.x, d4.y, d4.z, d4.w };
                int ss[4] = { s4.x, s4.y, s4.z, s4.w };
                unsigned tt[4] = { t0, t1, t2, t3 };
                #pragma unroll
                for (int j = 0; j < 4; j++) {
                    if (tt[j]) {
                        int slot = g_slot[dd[j]];
                        int pos = atomicAdd(&g_cnt[slot], 1);
                        if (pos < CAP) {
                            g_bin[slot * CAP + pos] = ss[j];
                        } else {
                            int op = atomicAdd(&g_nov, 1);
                            if (op < OV_CAP) { g_ov_src[op] = ss[j]; g_ov_slot[op] = slot; }
                        }
                    }
                }
            }
        }
    } else {
        // ---- s1c part: identical structure to the R11/R12-passing k_s ----
        int lane = threadIdx.x & 31;
        int half = lane >> 4;
        int l = lane & 15;
        int vb = blockIdx.x - EDGE_BLOCKS;
        int wg = (vb * 256 + threadIdx.x) >> 5;
        int nwarps = KS_BLOCKS * 8;
        float4 v1 = ((const float4*)g_v1)[l];
        float c1 = g_c1;
        for (int n = wg * 4; n < NNODES; n += nwarps * 4) {   // NNODES % 4 == 0
            int ra = n + half;
            int rb = n + 2 + half;
            float4 fa = feat4(ra, ue, ee)[l];
            float4 fb = feat4(rb, ue, ee)[l];
            float a1 = fa.x * v1.x + fa.y * v1.y + fa.z * v1.z + fa.w * v1.w;
            float b1 = fb.x * v1.x + fb.y * v1.y + fb.z * v1.z + fb.w * v1.w;
            #pragma unroll
            for (int o = 8; o; o >>= 1) {   // reduce within each half-warp
                a1 += __shfl_xor_sync(0xFFFFFFFFu, a1, o);
                b1 += __shfl_xor_sync(0xFFFFFFFFu, b1, o);
            }
            if (l == 0) {
                g_s1c[ra] = a1 + c1;
                g_s1c[rb] = b1 + c1;
            }
        }
    }
}

// -------- K2: warp-per-dst gather + fused epilogue + per-slot state cleanup --------
__global__ void __launch_bounds__(256) k_gather(const float* __restrict__ ue, const float* __restrict__ ee,
                                                const float* __restrict__ W1, const float* __restrict__ b1,
                                                const float* __restrict__ W2, const float* __restrict__ b2) {
    __shared__ float sW1[D * D], sW2[D * D], sb1[D], sb2[D];
    __shared__ float sg[8][D];
    int tid = threadIdx.x, lane = tid & 31, wid = tid >> 5;
    for (int i = tid; i < D * D; i += 256) { sW1[i] = W1[i]; sW2[i] = W2[i]; }
    for (int i = tid; i < D; i += 256) { sb1[i] = b1[i]; sb2[i] = b2[i]; }
    __syncthreads();
    float2 v2 = ((const float2*)g_v2)[lane];
    float c2 = g_c2;
    int nu = g_nuniq;
    int nov = g_nov;
    if (nov > OV_CAP) nov = OV_CAP;
    int wg = (blockIdx.x * blockDim.x + tid) >> 5;
    int nwarps = (gridDim.x * blockDim.x) >> 5;
    for (int q = wg; q < nu; q += nwarps) {
        int n = g_uniq[q];
        float2 hs = feat2(n, ue, ee)[lane];
        float p = hs.x * v2.x + hs.y * v2.y;   // s2[dst] from its own row (once per slot)
        #pragma unroll
        for (int o = 16; o; o >>= 1) p += __shfl_xor_sync(0xFFFFFFFFu, p, o);
        float s2d = p + c2;
        int deg = g_cnt[q];
        if (deg > CAP) deg = CAP;
        const int* bs = g_bin + q * CAP;
        float ax = 0.f, ay = 0.f, den = 0.f;
        int e = 0;
        for (; e + 3 < deg; e += 4) {          // 4-way MLP, no reductions
            int s0 = bs[e], s1i = bs[e + 1], s2i = bs[e + 2], s3i = bs[e + 3];
            float a0 = g_s1c[s0], a1 = g_s1c[s1i], a2 = g_s1c[s2i], a3 = g_s1c[s3i];
            float2 f0 = feat2(s0,  ue, ee)[lane];
            float2 f1 = feat2(s1i, ue, ee)[lane];
            float2 f2 = feat2(s2i, ue, ee)[lane];
            float2 f3 = feat2(s3i, ue, ee)[lane];
            float e0 = a0 + s2d; e0 = (e0 > 0.f) ? e0 : 0.2f * e0;
            float e1 = a1 + s2d; e1 = (e1 > 0.f) ? e1 : 0.2f * e1;
            float e2 = a2 + s2d; e2 = (e2 > 0.f) ? e2 : 0.2f * e2;
            float e3 = a3 + s2d; e3 = (e3 > 0.f) ? e3 : 0.2f * e3;
            float x0 = __expf(e0), x1 = __expf(e1), x2 = __expf(e2), x3 = __expf(e3);
            den += (x0 + x1) + (x2 + x3);
            ax += x0 * f0.x + x1 * f1.x + x2 * f2.x + x3 * f3.x;
            ay += x0 * f0.y + x1 * f1.y + x2 * f2.y + x3 * f3.y;
        }
        for (; e < deg; e++) {
            int s0 = bs[e];
            float a0 = g_s1c[s0];
            float2 f0 = feat2(s0, ue, ee)[lane];
            float e0 = a0 + s2d; e0 = (e0 > 0.f) ? e0 : 0.2f * e0;
            float x0 = __expf(e0);
            den += x0; ax += x0 * f0.x; ay += x0 * f0.y;
        }
        // overflow edges (normally nov == 0): direct scan
        for (int i = 0; i < nov; i++) {
            if (g_ov_slot[i] == q) {
                int s0 = g_ov_src[i];
                float a0 = g_s1c[s0];
                float2 f0 = feat2(s0, ue, ee)[lane];
                float e0 = a0 + s2d; e0 = (e0 > 0.f) ? e0 : 0.2f * e0;
                float x0 = __expf(e0);
                den += x0; ax += x0 * f0.x; ay += x0 * f0.y;
            }
        }
        // restore clean state for next replay (graph-deterministic)
        if (lane == 0) { g_cnt[q] = 0; g_flag[n >> 5] = 0u; }
        float inv = 1.f / (den + 1e-9f);
        float sden = den * inv;
        __syncwarp();
        sg[wid][2 * lane] = ax * inv;
        sg[wid][2 * lane + 1] = ay * inv;
        __syncwarp();
        float n0 = sden * sb1[2 * lane], n1 = sden * sb1[2 * lane + 1];
        #pragma unroll 16
        for (int k = 0; k < D; k++) {
            float gk = sg[wid][k];
            float2 wr = ((const float2*)(sW1 + k * D))[lane];
            n0 += gk * wr.x; n1 += gk * wr.y;
        }
        float sum0 = hs.x + n0, sum1 = hs.y + n1;
        float p0s = hs.x * n0, p1s = hs.y * n1;
        __syncwarp();
        sg[wid][2 * lane] = p0s;
        sg[wid][2 * lane + 1] = p1s;
        __syncwarp();
        float z0 = sum0 + sb2[2 * lane], z1 = sum1 + sb2[2 * lane + 1];
        #pragma unroll 16
        for (int k = 0; k < D; k++) {
            float pk = sg[wid][k];
            float2 wr = ((const float2*)(sW2 + k * D))[lane];
            z0 += pk * wr.x; z1 += pk * wr.y;
        }
        float h0 = (z0 > 0.f) ? z0 : 0.2f * z0;
        float h1 = (z1 > 0.f) ? z1 : 0.2f * z1;
        float ss = h0 * h0 + h1 * h1;
        #pragma unroll
        for (int o = 16; o; o >>= 1) ss += __shfl_xor_sync(0xFFFFFFFFu, ss, o);
        float invn = 1.f / fmaxf(sqrtf(ss), 1e-12f);
        float* orow = g_hd + (size_t)q * D;
        orow[2 * lane] = h0 * invn;
        orow[2 * lane + 1] = h1 * invn;
    }
}

// -------- K3: final pair dots (one pair per warp; 4096 concurrent chains) --------
__global__ void k_final(const int* __restrict__ uid, const int* __restrict__ iid,
                        const float* __restrict__ ue, const float* __restrict__ ee,
                        float* __restrict__ out) {
    if (blockIdx.x == 0 && threadIdx.x == 0) { g_nuniq = 0; g_nov = 0; }
    int lane = threadIdx.x & 31;
    int p = (blockIdx.x * blockDim.x + threadIdx.x) >> 5;   // one pair per warp
    if (p >= BATCH) return;
    int un = uid[p];
    int in = N_USERS + iid[p];
    float2 fu = feat2(un, ue, ee)[lane];
    float2 fi = feat2(in, ue, ee)[lane];
    float acc = fu.x * fi.x + fu.y * fi.y;
    int su = g_slot[un], si = g_slot[in];
    float2 hu = ((const float2*)(g_hd + (size_t)su * D))[lane];
    float2 hi = ((const float2*)(g_hd + (size_t)si * D))[lane];
    acc += hu.x * hi.x + hu.y * hi.y;
    #pragma unroll
    for (int o = 16; o; o >>= 1) acc += __shfl_xor_sync(0xFFFFFFFFu, acc, o);
    if (lane == 0) out[p] = acc;
}

extern "C" void kernel_launch(void* const* d_in, const int* in_sizes, int n_in,
                              void* d_out, int out_size) {
    const int* idx = (const int*)d_in[0];
    const int* uid = (const int*)d_in[1];
    const int* iid = (const int*)d_in[2];
    int base = (in_sizes[3] <= 2) ? 4 : 3;   // skip num_nodes scalar if present
    const float* ue = (const float*)d_in[base + 0];
    const float* ee = (const float*)d_in[base + 1];
    const float* Wa = (const float*)d_in[base + 2];
    const float* ba = (const float*)d_in[base + 3];
    const float* W1 = (const float*)d_in[base + 4];
    const float* b1 = (const float*)d_in[base + 5];
    const float* W2 = (const float*)d_in[base + 6];
    const float* b2 = (const float*)d_in[base + 7];
    const float* a  = (const float*)d_in[base + 8];
    float* out = (float*)d_out;
    (void)n_in; (void)out_size;

    k_mark<<<33, 256>>>(uid, iid, Wa, ba, a);
    k_stream<<<EDGE_BLOCKS + KS_BLOCKS, 256>>>(idx, ue, ee);
    k_gather<<<2048, 256>>>(ue, ee, W1, b1, W2, b2);
    k_final<<<512, 256>>>(uid, iid, ue, ee, out);
}